// round 16
// baseline (speedup 1.0000x reference)
#include <cuda_runtime.h>
#include <cuda_bf16.h>
#include <cuda_fp16.h>
#include <math.h>
#include <stdint.h>

#define SQ   2048
#define HID  1024
#define NH   16
#define HD   64
#define BSZ  2
#define MFREQ (SQ/2 + 1)
#define KTOP 15
#define PKS  3072
#define LOG2E 1.4426950408889634f

__device__ float d_c[SQ];
__device__ float d_dcflag;
__device__ int   d_maskflag;
__device__ float d_Vbuf[BSZ * SQ * HID];
__device__ float d_Comb[BSZ * SQ * HID];
__device__ float d_ac  [BSZ * NH * SQ];
__device__ int   d_topi[BSZ * NH * KTOP];
__device__ float d_topw[BSZ * NH * KTOP];

__device__ __nv_bfloat16 d_chi[SQ], d_clo[SQ];
__device__ __nv_bfloat16 d_Chi [SQ * SQ],        d_Clo [SQ * SQ];
__device__ __nv_bfloat16 d_Xhi [BSZ * SQ * HID], d_Xlo [BSZ * SQ * HID];
__device__ __nv_bfloat16 d_Xfhi[BSZ * SQ * HID], d_Xflo[BSZ * SQ * HID];
__device__ __half        d_QKVhi[BSZ * SQ * PKS], d_QKVlo[BSZ * SQ * PKS];
__device__ __half        d_Cbh [BSZ * SQ * HID];
__device__ __nv_bfloat16 d_Wchi[HID * PKS], d_Wclo[HID * PKS];
__device__ float         d_bcat[PKS];
__device__ __half        d_Woh[HID * HID], d_Wol[HID * HID];

__device__ __forceinline__ void cp_async16(void* smem, const void* gmem) {
    unsigned s = (unsigned)__cvta_generic_to_shared(smem);
    asm volatile("cp.async.cg.shared.global [%0], [%1], 16;" :: "r"(s), "l"(gmem));
}
__device__ __forceinline__ void cp_commit() { asm volatile("cp.async.commit_group;"); }
__device__ __forceinline__ void cp_wait0()  { asm volatile("cp.async.wait_group 0;"); }
__device__ __forceinline__ void cp_wait1()  { asm volatile("cp.async.wait_group 1;"); }

__device__ __forceinline__ void mma16816(float* d, const uint32_t* a, const uint32_t* b) {
    asm volatile(
        "mma.sync.aligned.m16n8k16.row.col.f32.bf16.bf16.f32 "
        "{%0,%1,%2,%3}, {%4,%5,%6,%7}, {%8,%9}, {%0,%1,%2,%3};"
        : "+f"(d[0]), "+f"(d[1]), "+f"(d[2]), "+f"(d[3])
        : "r"(a[0]), "r"(a[1]), "r"(a[2]), "r"(a[3]), "r"(b[0]), "r"(b[1]));
}
__device__ __forceinline__ void mma16816h(float* d, const uint32_t* a, const uint32_t* b) {
    asm volatile(
        "mma.sync.aligned.m16n8k16.row.col.f32.f16.f16.f32 "
        "{%0,%1,%2,%3}, {%4,%5,%6,%7}, {%8,%9}, {%0,%1,%2,%3};"
        : "+f"(d[0]), "+f"(d[1]), "+f"(d[2]), "+f"(d[3])
        : "r"(a[0]), "r"(a[1]), "r"(a[2]), "r"(a[3]), "r"(b[0]), "r"(b[1]));
}
__device__ __forceinline__ void ldsm_x4(uint32_t* r, uint32_t addr) {
    asm volatile("ldmatrix.sync.aligned.m8n8.x4.shared.b16 {%0,%1,%2,%3}, [%4];"
        : "=r"(r[0]), "=r"(r[1]), "=r"(r[2]), "=r"(r[3]) : "r"(addr));
}
__device__ __forceinline__ void ldsm_x4t(uint32_t* r, uint32_t addr) {
    asm volatile("ldmatrix.sync.aligned.m8n8.x4.trans.shared.b16 {%0,%1,%2,%3}, [%4];"
        : "=r"(r[0]), "=r"(r[1]), "=r"(r[2]), "=r"(r[3]) : "r"(addr));
}
__device__ __forceinline__ void ldsm_x2t(uint32_t* r, uint32_t addr) {
    asm volatile("ldmatrix.sync.aligned.m8n8.x2.trans.shared.b16 {%0,%1}, [%2];"
        : "=r"(r[0]), "=r"(r[1]) : "r"(addr));
}
__device__ __forceinline__ uint32_t pack_h2(float a, float b) {
    __half2 t = __floats2half2_rn(a, b);
    return *(uint32_t*)&t;
}

__global__ void filter_kernel(const int* __restrict__ li_p, const int* __restrict__ nl_p,
                              float* __restrict__ c, float* __restrict__ dcflag,
                              __nv_bfloat16* __restrict__ chi, __nv_bfloat16* __restrict__ clo)
{
    int n = blockIdx.x * blockDim.x + threadIdx.x;
    if (n >= SQ) return;
    int li = *li_p;
    int nl = *nl_p;
    const double ALPHA = 0.5;
    int M = MFREQ;
    int p, q;
    if (ALPHA <= 1.0 / (double)nl) {
        p = (int)(M * (1.0 - (double)(li + 1) / (double)nl));
        q = (int)((double)p + (double)M / (double)nl);
    } else {
        p = (nl > 1) ? (int)(M * (1.0 - ALPHA) * (1.0 - (double)li / (double)(nl - 1))) : 0;
        q = (int)((double)p + ALPHA * (double)M);
    }
    p = max(0, min(p, M - 1));
    q = max(p + 1, min(q, M));
    double acc = 0.0;
    const double w2 = 2.0 / (double)SQ, w1 = 1.0 / (double)SQ;
    const double tpn = 6.283185307179586476925286766559 * (double)n / (double)SQ;
    for (int f = p; f < q; f++) {
        double wf = (f == 0 || f == M - 1) ? w1 : w2;
        acc += wf * cos(tpn * (double)f);
    }
    float cf = (float)acc;
    c[n] = cf;
    __nv_bfloat16 h = __float2bfloat16_rn(cf);
    chi[n] = h;
    clo[n] = __float2bfloat16_rn(cf - __bfloat162float(h));
    if (n == 0) *dcflag = (p == 0) ? 1.0f : 0.0f;
}

__global__ void cmat_kernel(__nv_bfloat16* __restrict__ Chi, __nv_bfloat16* __restrict__ Clo,
                            const __nv_bfloat16* __restrict__ chi, const __nv_bfloat16* __restrict__ clo)
{
    int idx = blockIdx.x * blockDim.x + threadIdx.x;
    int t = idx >> 11, s = idx & (SQ - 1);
    int tau = (t - s) & (SQ - 1);
    Chi[idx] = chi[tau];
    Clo[idx] = clo[tau];
}

__global__ void split_kernel(const float* __restrict__ in,
                             __nv_bfloat16* __restrict__ hi, __nv_bfloat16* __restrict__ lo, int n)
{
    int i = blockIdx.x * blockDim.x + threadIdx.x;
    if (i >= n) return;
    float f = in[i];
    __nv_bfloat16 h = __float2bfloat16_rn(f);
    hi[i] = h;
    lo[i] = __float2bfloat16_rn(f - __bfloat162float(h));
}

__global__ void wsplith_kernel(const float* __restrict__ in,
                               __half* __restrict__ hi, __half* __restrict__ lo, int n)
{
    int i = blockIdx.x * blockDim.x + threadIdx.x;
    if (i >= n) return;
    float f = in[i];
    __half h = __float2half_rn(f);
    hi[i] = h;
    lo[i] = __float2half_rn(f - __half2float(h));
}

__global__ void wsplit_kernel(const float* __restrict__ in,
                              __nv_bfloat16* __restrict__ hi, __nv_bfloat16* __restrict__ lo,
                              int colOff)
{
    int i = blockIdx.x * blockDim.x + threadIdx.x;
    int r = i >> 10, c = i & (HID - 1);
    float f = in[i];
    __nv_bfloat16 h = __float2bfloat16_rn(f);
    size_t o = (size_t)r * PKS + colOff + c;
    hi[o] = h;
    lo[o] = __float2bfloat16_rn(f - __bfloat162float(h));
}

__global__ void bcat_kernel(const float* __restrict__ bq, const float* __restrict__ bk,
                            const float* __restrict__ bv, float* __restrict__ bcat)
{
    int i = blockIdx.x * blockDim.x + threadIdx.x;
    const float* src = (i < HID) ? bq : (i < 2 * HID ? bk : bv);
    bcat[i] = src[i & (HID - 1)];
}

__global__ void zero_kernel(float* __restrict__ p, int n)
{
    int i = blockIdx.x * blockDim.x + threadIdx.x;
    if (i < n) p[i] = 0.f;
}

__global__ void setflag_kernel(int* __restrict__ flag) { *flag = 0; }

__global__ void maskcheck_kernel(const float4* __restrict__ m, int n4, int* __restrict__ flag)
{
    int i = blockIdx.x * blockDim.x + threadIdx.x;
    int stride = gridDim.x * blockDim.x;
    bool nz = false;
    for (; i < n4; i += stride) {
        float4 v = m[i];
        nz = nz || (v.x != 0.f) || (v.y != 0.f) || (v.z != 0.f) || (v.w != 0.f);
    }
    if (__syncthreads_or(nz) && threadIdx.x == 0)
        atomicOr(flag, 1);
}

// ---------------- bf16-split HMMA GEMM; optional fp16/bf16 hi+lo output ----------------
#define GA_STR 40
#define GB_STR 136
#define A_BUF_ELEMS (128 * GA_STR)
#define B_BUF_ELEMS (32 * GB_STR)
__global__ __launch_bounds__(256) void gemm_bf16_kernel(
    const __nv_bfloat16* __restrict__ Ahi, const __nv_bfloat16* __restrict__ Alo,
    const __nv_bfloat16* __restrict__ Bhi, const __nv_bfloat16* __restrict__ Blo,
    const float* __restrict__ bias, const float* __restrict__ bscalep,
    float* __restrict__ C,
    void* __restrict__ OhiV, void* __restrict__ OloV, int outHalf,
    int loColMin, int loColMax,
    int M, int N, int Nb, int K,
    long long sA, long long sB, long long sC)
{
    extern __shared__ __nv_bfloat16 sm[];
    __nv_bfloat16* AsHi = sm;
    __nv_bfloat16* AsLo = sm + 2 * A_BUF_ELEMS;
    __nv_bfloat16* BsHi = sm + 4 * A_BUF_ELEMS;
    __nv_bfloat16* BsLo = sm + 4 * A_BUF_ELEMS + 2 * B_BUF_ELEMS;
    uint32_t sbase = (uint32_t)__cvta_generic_to_shared(sm);

    int z = blockIdx.z;
    Ahi += (size_t)z * sA;  Alo += (size_t)z * sA;
    Bhi += (size_t)z * sB;  Blo += (size_t)z * sB;
    if (C) C += (size_t)z * sC;
    __nv_bfloat16* OhiB = (__nv_bfloat16*)OhiV;
    __nv_bfloat16* OloB = (__nv_bfloat16*)OloV;
    __half* OhiH = (__half*)OhiV;
    __half* OloH = (__half*)OloV;
    if (OhiV) {
        OhiB += (size_t)z * sC; OloB += (size_t)z * sC;
        OhiH += (size_t)z * sC; OloH += (size_t)z * sC;
    }

    int tid = threadIdx.x;
    int lane = tid & 31;
    int wid = tid >> 5;
    int mBase = (wid >> 2) * 64;
    int nBase = (wid & 3) * 32;
    int row0 = blockIdx.y * 128;
    int col0 = blockIdx.x * 128;

    float acc[4][4][4];
#pragma unroll
    for (int mf = 0; mf < 4; mf++)
#pragma unroll
        for (int nf = 0; nf < 4; nf++)
#pragma unroll
            for (int r = 0; r < 4; r++) acc[mf][nf][r] = 0.f;

    int ar = tid >> 1;
    int br = tid >> 3;
    const __nv_bfloat16* Ah0 = Ahi + (size_t)(row0 + ar) * K;
    const __nv_bfloat16* Al0 = Alo + (size_t)(row0 + ar) * K;

#define LOAD_TILES(buf, k0)                                                             \
    do {                                                                                \
        _Pragma("unroll")                                                               \
        for (int j = 0; j < 2; j++) {                                                   \
            int s = (tid & 1) * 2 + j;                                                  \
            cp_async16(&AsHi[(buf) * A_BUF_ELEMS + ar * GA_STR + s * 8],                \
                       Ah0 + (k0) + s * 8);                                             \
            cp_async16(&AsLo[(buf) * A_BUF_ELEMS + ar * GA_STR + s * 8],                \
                       Al0 + (k0) + s * 8);                                             \
            int sb = (tid & 7) * 2 + j;                                                 \
            cp_async16(&BsHi[(buf) * B_BUF_ELEMS + br * GB_STR + sb * 8],               \
                       Bhi + (size_t)((k0) + br) * Nb + col0 + sb * 8);                 \
            cp_async16(&BsLo[(buf) * B_BUF_ELEMS + br * GB_STR + sb * 8],               \
                       Blo + (size_t)((k0) + br) * Nb + col0 + sb * 8);                 \
        }                                                                               \
    } while (0)

    LOAD_TILES(0, 0);
    cp_commit();
    cp_wait0();
    __syncthreads();

    int nIter = K >> 5;
    int lr = lane & 15;
    int khalf = (lane >> 4) << 3;

    for (int it = 0; it < nIter; it++) {
        int buf = it & 1;
        if (it + 1 < nIter) {
            LOAD_TILES(buf ^ 1, (it + 1) << 5);
            cp_commit();
        }
        uint32_t aHiB = sbase + 2 * (buf * A_BUF_ELEMS);
        uint32_t aLoB = sbase + 2 * (2 * A_BUF_ELEMS + buf * A_BUF_ELEMS);
        uint32_t bHiB = sbase + 2 * (4 * A_BUF_ELEMS + buf * B_BUF_ELEMS);
        uint32_t bLoB = sbase + 2 * (4 * A_BUF_ELEMS + 2 * B_BUF_ELEMS + buf * B_BUF_ELEMS);
#pragma unroll
        for (int ks = 0; ks < 32; ks += 16) {
            uint32_t ahi[4][4], alo[4][4], bhi[4][2], blo[4][2];
#pragma unroll
            for (int mf = 0; mf < 4; mf++) {
                uint32_t off = 2 * ((mBase + mf * 16 + lr) * GA_STR + ks + khalf);
                ldsm_x4(ahi[mf], aHiB + off);
                ldsm_x4(alo[mf], aLoB + off);
            }
#pragma unroll
            for (int nf = 0; nf < 4; nf++) {
                uint32_t off = 2 * ((ks + lr) * GB_STR + nBase + nf * 8);
                ldsm_x2t(bhi[nf], bHiB + off);
                ldsm_x2t(blo[nf], bLoB + off);
            }
#pragma unroll
            for (int mf = 0; mf < 4; mf++)
#pragma unroll
                for (int nf = 0; nf < 4; nf++) {
                    mma16816(acc[mf][nf], ahi[mf], bhi[nf]);
                    mma16816(acc[mf][nf], ahi[mf], blo[nf]);
                    mma16816(acc[mf][nf], alo[mf], bhi[nf]);
                }
        }
        if (it + 1 < nIter) cp_wait0();
        __syncthreads();
    }

    float bscale = 0.f;
    if (bias) bscale = bscalep ? *bscalep : 1.f;

#pragma unroll
    for (int mf = 0; mf < 4; mf++) {
        int r0 = row0 + mBase + mf * 16 + (lane >> 2);
#pragma unroll
        for (int nf = 0; nf < 4; nf++) {
            int c0 = col0 + nBase + nf * 8 + (lane & 3) * 2;
            float b0 = 0.f, b1 = 0.f;
            if (bias) { b0 = bias[c0] * bscale; b1 = bias[c0 + 1] * bscale; }
            float v0 = acc[mf][nf][0] + b0, v1 = acc[mf][nf][1] + b1;
            float v2 = acc[mf][nf][2] + b0, v3 = acc[mf][nf][3] + b1;
            if (C) {
                float2 w0 = {v0, v1}, w1 = {v2, v3};
                *(float2*)&C[(size_t)r0 * N + c0]       = w0;
                *(float2*)&C[(size_t)(r0 + 8) * N + c0] = w1;
            }
            if (OhiV) {
                bool wantLo = (c0 >= loColMin) && (c0 < loColMax);
                if (outHalf) {
                    __half h0 = __float2half_rn(v0), h1 = __float2half_rn(v1);
                    __half h2 = __float2half_rn(v2), h3 = __float2half_rn(v3);
                    __half2 hv0 = {h0, h1}, hv1 = {h2, h3};
                    *(__half2*)&OhiH[(size_t)r0 * N + c0]       = hv0;
                    *(__half2*)&OhiH[(size_t)(r0 + 8) * N + c0] = hv1;
                    if (wantLo) {
                        __half2 lv0 = {__float2half_rn(v0 - __half2float(h0)),
                                       __float2half_rn(v1 - __half2float(h1))};
                        __half2 lv1 = {__float2half_rn(v2 - __half2float(h2)),
                                       __float2half_rn(v3 - __half2float(h3))};
                        *(__half2*)&OloH[(size_t)r0 * N + c0]       = lv0;
                        *(__half2*)&OloH[(size_t)(r0 + 8) * N + c0] = lv1;
                    }
                } else {
                    __nv_bfloat16 h0 = __float2bfloat16_rn(v0), h1 = __float2bfloat16_rn(v1);
                    __nv_bfloat16 h2 = __float2bfloat16_rn(v2), h3 = __float2bfloat16_rn(v3);
                    __nv_bfloat162 hv0 = {h0, h1}, hv1 = {h2, h3};
                    *(__nv_bfloat162*)&OhiB[(size_t)r0 * N + c0]       = hv0;
                    *(__nv_bfloat162*)&OhiB[(size_t)(r0 + 8) * N + c0] = hv1;
                    if (wantLo) {
                        __nv_bfloat162 lv0 = {__float2bfloat16_rn(v0 - __bfloat162float(h0)),
                                              __float2bfloat16_rn(v1 - __bfloat162float(h1))};
                        __nv_bfloat162 lv1 = {__float2bfloat16_rn(v2 - __bfloat162float(h2)),
                                              __float2bfloat16_rn(v3 - __bfloat162float(h3))};
                        *(__nv_bfloat162*)&OloB[(size_t)r0 * N + c0]       = lv0;
                        *(__nv_bfloat162*)&OloB[(size_t)(r0 + 8) * N + c0] = lv1;
                    }
                }
            }
        }
    }
}

// ---------------- fp16 2-term GEMM (outproj) ----------------
__global__ __launch_bounds__(256) void gemm_f16_kernel(
    const __half* __restrict__ Ah, const __half* __restrict__ Bhi, const __half* __restrict__ Blo,
    const float* __restrict__ bias, float* __restrict__ C, int M, int N, int K)
{
    extern __shared__ __half smh[];
    __half* AsH  = smh;
    __half* BsHi = smh + 2 * A_BUF_ELEMS;
    __half* BsLo = smh + 2 * A_BUF_ELEMS + 2 * B_BUF_ELEMS;
    uint32_t sbase = (uint32_t)__cvta_generic_to_shared(smh);

    int tid = threadIdx.x;
    int lane = tid & 31;
    int wid = tid >> 5;
    int mBase = (wid >> 2) * 64;
    int nBase = (wid & 3) * 32;
    int row0 = blockIdx.y * 128;
    int col0 = blockIdx.x * 128;

    float acc[4][4][4];
#pragma unroll
    for (int mf = 0; mf < 4; mf++)
#pragma unroll
        for (int nf = 0; nf < 4; nf++)
#pragma unroll
            for (int r = 0; r < 4; r++) acc[mf][nf][r] = 0.f;

    int ar = tid >> 1;
    int br = tid >> 3;
    const __half* A0 = Ah + (size_t)(row0 + ar) * K;

#define LOAD_TILES_H(buf, k0)                                                           \
    do {                                                                                \
        _Pragma("unroll")                                                               \
        for (int j = 0; j < 2; j++) {                                                   \
            int s = (tid & 1) * 2 + j;                                                  \
            cp_async16(&AsH[(buf) * A_BUF_ELEMS + ar * GA_STR + s * 8],                 \
                       A0 + (k0) + s * 8);                                              \
            int sb = (tid & 7) * 2 + j;                                                 \
            cp_async16(&BsHi[(buf) * B_BUF_ELEMS + br * GB_STR + sb * 8],               \
                       Bhi + (size_t)((k0) + br) * N + col0 + sb * 8);                  \
            cp_async16(&BsLo[(buf) * B_BUF_ELEMS + br * GB_STR + sb * 8],               \
                       Blo + (size_t)((k0) + br) * N + col0 + sb * 8);                  \
        }                                                                               \
    } while (0)

    LOAD_TILES_H(0, 0);
    cp_commit();
    cp_wait0();
    __syncthreads();

    int nIter = K >> 5;
    int lr = lane & 15;
    int khalf = (lane >> 4) << 3;

    for (int it = 0; it < nIter; it++) {
        int buf = it & 1;
        if (it + 1 < nIter) {
            LOAD_TILES_H(buf ^ 1, (it + 1) << 5);
            cp_commit();
        }
        uint32_t aB   = sbase + 2 * (buf * A_BUF_ELEMS);
        uint32_t bHiB = sbase + 2 * (2 * A_BUF_ELEMS + buf * B_BUF_ELEMS);
        uint32_t bLoB = sbase + 2 * (2 * A_BUF_ELEMS + 2 * B_BUF_ELEMS + buf * B_BUF_ELEMS);
#pragma unroll
        for (int ks = 0; ks < 32; ks += 16) {
            uint32_t ah[4][4], bhi[4][2], blo[4][2];
#pragma unroll
            for (int mf = 0; mf < 4; mf++) {
                uint32_t off = 2 * ((mBase + mf * 16 + lr) * GA_STR + ks + khalf);
                ldsm_x4(ah[mf], aB + off);
            }
#pragma unroll
            for (int nf = 0; nf < 4; nf++) {
                uint32_t off = 2 * ((ks + lr) * GB_STR + nBase + nf * 8);
                ldsm_x2t(bhi[nf], bHiB + off);
                ldsm_x2t(blo[nf], bLoB + off);
            }
#pragma unroll
            for (int mf = 0; mf < 4; mf++)
#pragma unroll
                for (int nf = 0; nf < 4; nf++) {
                    mma16816h(acc[mf][nf], ah[mf], bhi[nf]);
                    mma16816h(acc[mf][nf], ah[mf], blo[nf]);
                }
        }
        if (it + 1 < nIter) cp_wait0();
        __syncthreads();
    }

#pragma unroll
    for (int mf = 0; mf < 4; mf++) {
        int r0 = row0 + mBase + mf * 16 + (lane >> 2);
#pragma unroll
        for (int nf = 0; nf < 4; nf++) {
            int c0 = col0 + nBase + nf * 8 + (lane & 3) * 2;
            float b0 = bias[c0], b1 = bias[c0 + 1];
            float2 w0 = { acc[mf][nf][0] + b0, acc[mf][nf][1] + b1 };
            float2 w1 = { acc[mf][nf][2] + b0, acc[mf][nf][3] + b1 };
            *(float2*)&C[(size_t)r0 * N + c0]       = w0;
            *(float2*)&C[(size_t)(r0 + 8) * N + c0] = w1;
        }
    }
}

// ---------------- fp16 flash attention: 2-term QK, 1-term PV, exp2 softmax ----------------
#define FSTR 72
#define Q_ELEMS (128 * FSTR)
#define KV_BASE (2 * Q_ELEMS)
#define KV_ONE  (64 * FSTR)
#define KV_STRIDE (3 * KV_ONE)
#define SCS 66
#define ACB_OFF (2 * (KV_BASE + 2 * KV_STRIDE))
#define FLASH_SMEM (ACB_OFF + SQ * 4)
__global__ __launch_bounds__(256, 2) void flash_kernel(
    const __half* __restrict__ QKVhi, const __half* __restrict__ QKVlo,
    const float* __restrict__ mask, const int* __restrict__ maskflag,
    float* __restrict__ Comb, float* __restrict__ ac)
{
    extern __shared__ __half smh[];
    float* Stile = (float*)smh;
    float* acb   = (float*)((char*)smh + ACB_OFF);
    uint32_t sbase = (uint32_t)__cvta_generic_to_shared(smh);

    int tid = threadIdx.x;
    int lane = tid & 31, wid = tid >> 5;
    int qb = blockIdx.x, h = blockIdx.y, b = blockIdx.z;
    int t0 = qb * 128;
    int wr = wid * 16;
    const int useMask = *maskflag;
    const float SCL = 0.125f * LOG2E;   // log2-domain score scale

    size_t base = (size_t)b * SQ * PKS + h * HD;
    const __half* Qh = QKVhi + base;
    const __half* Kh = QKVhi + base + HID;
    const __half* Kl = QKVlo + base + HID;
    const __half* Vh = QKVhi + base + 2 * HID;
    const float* Mbase = mask + (size_t)b * SQ * SQ;
    float* acrow = ac + (size_t)(b * NH + h) * SQ;

#define LOAD_KV(bufi, kti)                                                              \
    do {                                                                                \
        int s0_ = (kti) * 64;                                                           \
        unsigned kvo_ = KV_BASE + (bufi) * KV_STRIDE;                                   \
        _Pragma("unroll")                                                               \
        for (int kk = 0; kk < 2; kk++) {                                                \
            int id_ = tid + kk * 256;                                                   \
            int r_ = id_ >> 3, c8_ = (id_ & 7) * 8;                                     \
            size_t src_ = (size_t)(s0_ + r_) * PKS + c8_;                               \
            unsigned dst_ = kvo_ + r_ * FSTR + c8_;                                     \
            cp_async16(&smh[dst_],              Kh + src_);                             \
            cp_async16(&smh[dst_ + KV_ONE],     Kl + src_);                             \
            cp_async16(&smh[dst_ + 2 * KV_ONE], Vh + src_);                             \
        }                                                                               \
    } while (0)

#pragma unroll
    for (int k = 0; k < 4; k++) {
        int id = tid + k * 256;
        int r = id >> 3, c8 = (id & 7) * 8;
        cp_async16(&smh[r * FSTR + c8], Qh + (size_t)(t0 + r) * PKS + c8);
    }
    cp_commit();
    LOAD_KV(0, 0);
    cp_commit();
    for (int i = tid; i < SQ; i += 256) acb[i] = 0.f;
    cp_wait1();
    __syncthreads();

    uint32_t qh[4][4];
    int lr = lane & 15, kh8 = (lane >> 4) * 8;
#pragma unroll
    for (int ks = 0; ks < 4; ks++)
        ldsm_x4(qh[ks], sbase + 2 * ((wr + lr) * FSTR + ks * 16 + kh8));
    cp_wait0();
    __syncthreads();

    float m0 = -INFINITY, m1 = -INFINITY, l0 = 0.f, l1 = 0.f;
    float o[8][4];
#pragma unroll
    for (int df = 0; df < 8; df++)
#pragma unroll
        for (int r = 0; r < 4; r++) o[df][r] = 0.f;

    int r4 = lane >> 2, c2 = (lane & 3) * 2;
    int qrow = t0 + wr + r4;
    int krL = ((lane >> 4) << 3) | (lane & 7);
    int kdL = ((lane >> 3) & 1) << 3;
    int vRow = lane & 15;
    int vSel = lane >> 4;

    int du = tid - 63;
    int drlo = du > 0 ? du : 0;
    int drhi = (du + 64 < 128) ? du + 64 : 128;
    const float* dbase = Stile - du;

    for (int kt = 0; kt < 32; kt++) {
        int s0 = kt * 64;
        int buf = kt & 1;
        bool has_next = (kt + 1 < 32);
        if (has_next) {
            LOAD_KV(buf ^ 1, kt + 1);
            cp_commit();
        }

        uint32_t kvbK = sbase + 2 * (KV_BASE + buf * KV_STRIDE);
        uint32_t kvbV = kvbK + 2 * (2 * KV_ONE);

        float s[8][4];
#pragma unroll
        for (int nf = 0; nf < 8; nf++)
#pragma unroll
            for (int r = 0; r < 4; r++) s[nf][r] = 0.f;
#pragma unroll
        for (int ks = 0; ks < 4; ks++) {
#pragma unroll
            for (int nf2 = 0; nf2 < 8; nf2 += 2) {
                uint32_t ko = kvbK + 2 * ((nf2 * 8 + krL) * FSTR + ks * 16 + kdL);
                uint32_t bh[4], bl[4];
                ldsm_x4(bh, ko);
                ldsm_x4(bl, ko + 2 * KV_ONE);
                mma16816h(s[nf2],     qh[ks], &bh[0]);
                mma16816h(s[nf2],     qh[ks], &bl[0]);
                mma16816h(s[nf2 + 1], qh[ks], &bh[2]);
                mma16816h(s[nf2 + 1], qh[ks], &bl[2]);
            }
        }

        // stage RAW scores for the diag phase
        {
            float* Sw0 = Stile + (wr + r4) * SCS + c2;
            float* Sw1 = Sw0 + 8 * SCS;
#pragma unroll
            for (int nf = 0; nf < 8; nf++) {
                float2 w0 = { s[nf][0], s[nf][1] };
                float2 w1 = { s[nf][2], s[nf][3] };
                *(float2*)(Sw0 + nf * 8) = w0;
                *(float2*)(Sw1 + nf * 8) = w1;
            }
        }

        // log2-domain scale + (optional) mask + row max
        const float* mrow0 = Mbase + (size_t)qrow * SQ + s0 + c2;
        const float* mrow1 = mrow0 + 8 * SQ;
        float mx0 = -INFINITY, mx1 = -INFINITY;
#pragma unroll
        for (int nf = 0; nf < 8; nf++) {
            float2 ma = {0.f, 0.f}, mb2 = {0.f, 0.f};
            if (useMask) {
                ma  = *(const float2*)(mrow0 + nf * 8);
                mb2 = *(const float2*)(mrow1 + nf * 8);
                ma.x *= LOG2E; ma.y *= LOG2E; mb2.x *= LOG2E; mb2.y *= LOG2E;
            }
            s[nf][0] = s[nf][0] * SCL + ma.x;
            s[nf][1] = s[nf][1] * SCL + ma.y;
            s[nf][2] = s[nf][2] * SCL + mb2.x;
            s[nf][3] = s[nf][3] * SCL + mb2.y;
            mx0 = fmaxf(mx0, fmaxf(s[nf][0], s[nf][1]));
            mx1 = fmaxf(mx1, fmaxf(s[nf][2], s[nf][3]));
        }
        mx0 = fmaxf(mx0, __shfl_xor_sync(0xffffffffu, mx0, 1));
        mx0 = fmaxf(mx0, __shfl_xor_sync(0xffffffffu, mx0, 2));
        mx1 = fmaxf(mx1, __shfl_xor_sync(0xffffffffu, mx1, 1));
        mx1 = fmaxf(mx1, __shfl_xor_sync(0xffffffffu, mx1, 2));
        float nm0 = fmaxf(m0, mx0), nm1 = fmaxf(m1, mx1);
        float cor0 = exp2f(m0 - nm0), cor1 = exp2f(m1 - nm1);
        m0 = nm0; m1 = nm1;

        uint32_t pa[4][4];
        float rs0 = 0.f, rs1 = 0.f;
#pragma unroll
        for (int kc = 0; kc < 4; kc++) {
            int n0 = 2 * kc, n1 = 2 * kc + 1;
            pa[kc][0] = pack_h2(exp2f(s[n0][0] - nm0), exp2f(s[n0][1] - nm0));
            pa[kc][1] = pack_h2(exp2f(s[n0][2] - nm1), exp2f(s[n0][3] - nm1));
            pa[kc][2] = pack_h2(exp2f(s[n1][0] - nm0), exp2f(s[n1][1] - nm0));
            pa[kc][3] = pack_h2(exp2f(s[n1][2] - nm1), exp2f(s[n1][3] - nm1));
            float2 u;
            u = __half22float2(*(__half2*)&pa[kc][0]); rs0 += u.x + u.y;
            u = __half22float2(*(__half2*)&pa[kc][2]); rs0 += u.x + u.y;
            u = __half22float2(*(__half2*)&pa[kc][1]); rs1 += u.x + u.y;
            u = __half22float2(*(__half2*)&pa[kc][3]); rs1 += u.x + u.y;
        }
        rs0 += __shfl_xor_sync(0xffffffffu, rs0, 1);
        rs0 += __shfl_xor_sync(0xffffffffu, rs0, 2);
        rs1 += __shfl_xor_sync(0xffffffffu, rs1, 1);
        rs1 += __shfl_xor_sync(0xffffffffu, rs1, 2);
        l0 = l0 * cor0 + rs0;
        l1 = l1 * cor1 + rs1;
#pragma unroll
        for (int df = 0; df < 8; df++) {
            o[df][0] *= cor0; o[df][1] *= cor0;
            o[df][2] *= cor1; o[df][3] *= cor1;
        }

#pragma unroll
        for (int kc = 0; kc < 4; kc++) {
#pragma unroll
            for (int df2 = 0; df2 < 8; df2 += 2) {
                uint32_t vo = kvbV + 2 * ((kc * 16 + vRow) * FSTR + (df2 + vSel) * 8);
                uint32_t vh[4];
                ldsm_x4t(vh, vo);
                mma16816h(o[df2],     pa[kc], &vh[0]);
                mma16816h(o[df2 + 1], pa[kc], &vh[2]);
            }
        }
        __syncthreads();

        if (tid < 191) {
            float sa = 0.f, sb = 0.f;
            int r = drlo;
            for (; r + 1 < drhi; r += 2) {
                sa += dbase[r * (SCS + 1)];
                sb += dbase[r * (SCS + 1) + (SCS + 1)];
            }
            if (r < drhi) sa += dbase[r * (SCS + 1)];
            int tau = (t0 - s0 + du) & (SQ - 1);
            acb[tau] += (sa + sb) * (1.f / 64.f);
        }
        if (has_next) cp_wait0();
        __syncthreads();
    }

    for (int i = tid; i < SQ; i += 256)
        atomicAdd(&acrow[i], acb[i]);

    float inv0 = 0.5f / l0, inv1 = 0.5f / l1;
    float* C0 = Comb + (size_t)b * SQ * HID + (size_t)qrow * HID + h * HD + c2;
#pragma unroll
    for (int df = 0; df < 8; df++) {
        float2 va = { o[df][0] * inv0, o[df][1] * inv0 };
        float2 vb = { o[df][2] * inv1, o[df][3] * inv1 };
        *(float2*)(C0 + df * 8)            = va;
        *(float2*)(C0 + 8 * HID + df * 8)  = vb;
    }
}

// ---------------- top-k ----------------
__global__ __launch_bounds__(256) void topk_kernel(
    const float* __restrict__ ac, int* __restrict__ topi, float* __restrict__ topw)
{
    int bh = blockIdx.x;
    __shared__ float svv[SQ];
    __shared__ float rv[256];
    __shared__ int ri[256];
    __shared__ float tvals[KTOP];
    __shared__ int tidxs[KTOP];
    int tid = threadIdx.x;

    for (int i = tid; i < SQ; i += 256)
        svv[i] = ac[(size_t)bh * SQ + i];
    __syncthreads();

    for (int t = 0; t < KTOP; t++) {
        float bv = -INFINITY;
        int bi = 0;
        for (int i = tid; i < SQ; i += 256) {
            float v = svv[i];
            if (v > bv || (v == bv && i < bi)) { bv = v; bi = i; }
        }
        rv[tid] = bv; ri[tid] = bi;
        __syncthreads();
        for (int st = 128; st > 0; st >>= 1) {
            if (tid < st) {
                float v2 = rv[tid + st]; int i2 = ri[tid + st];
                if (v2 > rv[tid] || (v2 == rv[tid] && i2 < ri[tid])) { rv[tid] = v2; ri[tid] = i2; }
            }
            __syncthreads();
        }
        if (tid == 0) {
            tvals[t] = rv[0]; tidxs[t] = ri[0];
            svv[ri[0]] = -INFINITY;
        }
        __syncthreads();
    }

    if (tid == 0) {
        float mx = tvals[0];
        float e[KTOP], ssum = 0.f;
#pragma unroll
        for (int t = 0; t < KTOP; t++) { e[t] = __expf(tvals[t] - mx); ssum += e[t]; }
        float inv = 1.f / ssum;
#pragma unroll
        for (int t = 0; t < KTOP; t++) {
            topw[bh * KTOP + t] = e[t] * inv;
            topi[bh * KTOP + t] = tidxs[t];
        }
    }
}

// ---------------- freq gather -> fp16 Cb for outproj ----------------
__global__ __launch_bounds__(256) void freq_kernel(
    const float* __restrict__ V, const int* __restrict__ topi,
    const float* __restrict__ topw, const float* __restrict__ Comb,
    __half* __restrict__ Cbh)
{
    int t = blockIdx.x, b = blockIdx.y;
    __shared__ int si[NH * KTOP];
    __shared__ float sw[NH * KTOP];
    int tid = threadIdx.x;
    if (tid < NH * KTOP) {
        si[tid] = topi[b * NH * KTOP + tid];
        sw[tid] = topw[b * NH * KTOP + tid];
    }
    __syncthreads();

    int c = tid * 4;
    int h = c >> 6;
    size_t off = ((size_t)b * SQ + t) * HID + c;
    float4 acc = *(const float4*)&Comb[off];
    const float* Vb = V + (size_t)b * SQ * HID;
#pragma unroll
    for (int j = 0; j < KTOP; j++) {
        int row = (t + si[h * KTOP + j]) & (SQ - 1);
        float w = 0.5f * sw[h * KTOP + j];
        float4 v = *(const float4*)&Vb[(size_t)row * HID + c];
        acc.x += w * v.x; acc.y += w * v.y; acc.z += w * v.z; acc.w += w * v.w;
    }
    *(__half2*)&Cbh[off]     = __floats2half2_rn(acc.x, acc.y);
    *(__half2*)&Cbh[off + 2] = __floats2half2_rn(acc.z, acc.w);
}

// ---------------- launcher (maskcheck + Vbuf/Wo on side stream) ----------------
extern "C" void kernel_launch(void* const* d_in, const int* in_sizes, int n_in,
                              void* d_out, int out_size)
{
    const float* X    = (const float*)d_in[0];
    const float* mask = (const float*)d_in[1];
    const float* Wq   = (const float*)d_in[2];
    const float* bq   = (const float*)d_in[3];
    const float* Wk   = (const float*)d_in[4];
    const float* bk   = (const float*)d_in[5];
    const float* Wv   = (const float*)d_in[6];
    const float* bv   = (const float*)d_in[7];
    const float* Wo   = (const float*)d_in[8];
    const float* bo   = (const float*)d_in[9];
    const int*   li   = (const int*)d_in[10];
    const int*   nl   = (const int*)d_in[11];
    float* out = (float*)d_out;

    float *cP, *dcP, *VbP, *CbP, *acP, *twP, *bcatP;
    int *tiP, *mfP;
    __nv_bfloat16 *chiP, *cloP, *ChiP, *CloP, *XhiP, *XloP, *XfhiP, *XfloP;
    __nv_bfloat16 *WchiP, *WcloP;
    __half *QKVhiP, *QKVloP, *CbhP, *WohP, *WolP;
    cudaGetSymbolAddress((void**)&cP,  d_c);
    cudaGetSymbolAddress((void**)&dcP, d_dcflag);
    cudaGetSymbolAddress((void**)&mfP, d_maskflag);
    cudaGetSymbolAddress((void**)&VbP, d_Vbuf);
    cudaGetSymbolAddress((void**)&CbP, d_Comb);
    cudaGetSymbolAddress((void**)&acP, d_ac);
    cudaGetSymbolAddress((void**)&tiP, d_topi);
    cudaGetSymbolAddress((void**)&twP, d_topw);
    cudaGetSymbolAddress((void**)&bcatP, d_bcat);
    cudaGetSymbolAddress((void**)&chiP, d_chi);
    cudaGetSymbolAddress((void**)&cloP, d_clo);
    cudaGetSymbolAddress((void**)&ChiP, d_Chi);
    cudaGetSymbolAddress((void**)&CloP, d_Clo);
    cudaGetSymbolAddress((void**)&XhiP, d_Xhi);
    cudaGetSymbolAddress((void**)&XloP, d_Xlo);
    cudaGetSymbolAddress((void**)&XfhiP, d_Xfhi);
    cudaGetSymbolAddress((void**)&XfloP, d_Xflo);
    cudaGetSymbolAddress((void**)&QKVhiP, d_QKVhi);
    cudaGetSymbolAddress((void**)&QKVloP, d_QKVlo);
    cudaGetSymbolAddress((void**)&CbhP, d_Cbh);
    cudaGetSymbolAddress((void**)&WchiP, d_Wchi);
    cudaGetSymbolAddress((void**)&WcloP, d_Wclo);
    cudaGetSymbolAddress((void**)&WohP, d_Woh);
    cudaGetSymbolAddress((void**)&WolP, d_Wol);

    const long long SH  = (long long)SQ * HID;
    const long long SH3 = (long long)SQ * PKS;
    const int NELT = BSZ * SQ * HID;
    const int WELT = HID * HID;

    static cudaStream_t s2 = nullptr;
    static cudaEvent_t evStart = nullptr, evMask = nullptr, evFork = nullptr, evJoin = nullptr;
    static bool init_done = false;
    if (!init_done) {
        cudaFuncSetAttribute(gemm_bf16_kernel, cudaFuncAttributeMaxDynamicSharedMemorySize, 75776);
        cudaFuncSetAttribute(gemm_f16_kernel,  cudaFuncAttributeMaxDynamicSharedMemorySize, 55296);
        cudaFuncSetAttribute(flash_kernel,     cudaFuncAttributeMaxDynamicSharedMemorySize, FLASH_SMEM);
        cudaStreamCreateWithFlags(&s2, cudaStreamNonBlocking);
        cudaEventCreateWithFlags(&evStart, cudaEventDisableTiming);
        cudaEventCreateWithFlags(&evMask,  cudaEventDisableTiming);
        cudaEventCreateWithFlags(&evFork,  cudaEventDisableTiming);
        cudaEventCreateWithFlags(&evJoin,  cudaEventDisableTiming);
        init_done = true;
    }

    // side stream from t=0: mask scan (only flash needs the flag)
    cudaEventRecord(evStart, 0);
    cudaStreamWaitEvent(s2, evStart, 0);
    setflag_kernel<<<1, 1, 0, s2>>>(mfP);
    maskcheck_kernel<<<2048, 256, 0, s2>>>((const float4*)mask, BSZ * SQ * SQ / 4, mfP);
    cudaEventRecord(evMask, s2);

    // main: prep chain
    filter_kernel<<<8, 256>>>(li, nl, cP, dcP, chiP, cloP);
    cmat_kernel<<<(SQ * SQ) / 256, 256>>>(ChiP, CloP, chiP, cloP);
    split_kernel<<<NELT / 256, 256>>>(X, XhiP, XloP, NELT);
    wsplit_kernel<<<WELT / 256, 256>>>(Wq, WchiP, WcloP, 0);
    wsplit_kernel<<<WELT / 256, 256>>>(Wk, WchiP, WcloP, HID);
    wsplit_kernel<<<WELT / 256, 256>>>(Wv, WchiP, WcloP, 2 * HID);
    bcat_kernel<<<PKS / 256, 256>>>(bq, bk, bv, bcatP);

    // fork: side stream computes Vbuf + Wo split (after mask scan)
    cudaEventRecord(evFork, 0);
    cudaStreamWaitEvent(s2, evFork, 0);
    gemm_bf16_kernel<<<dim3(HID / 128, SQ / 128, BSZ), 256, 75776, s2>>>(
        XhiP, XloP, WchiP + 2 * HID, WcloP + 2 * HID, bv, nullptr, VbP,
        nullptr, nullptr, 0, 0, 0, SQ, HID, PKS, HID, SH, 0, SH);
    wsplith_kernel<<<WELT / 256, 256, 0, s2>>>(Wo, WohP, WolP, WELT);
    cudaEventRecord(evJoin, s2);

    // main: Xf = C @ X -> bf16 hi/lo
    gemm_bf16_kernel<<<dim3(HID / 128, SQ / 128, BSZ), 256, 75776>>>(
        ChiP, CloP, XhiP, XloP, nullptr, nullptr, nullptr,
        XfhiP, XfloP, 0, 0, HID, SQ, HID, HID, SQ, 0, SH, SH);

    // merged Q|K|V projections -> fp16 QKV; lo only for K columns
    gemm_bf16_kernel<<<dim3(PKS / 128, SQ / 128, BSZ), 256, 75776>>>(
        XfhiP, XfloP, WchiP, WcloP, bcatP, dcP, nullptr,
        QKVhiP, QKVloP, 1, HID, 2 * HID, SQ, PKS, PKS, HID, SH, 0, SH3);

    zero_kernel<<<(BSZ * NH * SQ) / 256, 256>>>(acP, BSZ * NH * SQ);
    cudaStreamWaitEvent(0, evMask, 0);
    flash_kernel<<<dim3(SQ / 128, NH, BSZ), 256, FLASH_SMEM>>>(
        QKVhiP, QKVloP, mask, mfP, CbP, acP);

    topk_kernel<<<BSZ * NH, 256>>>(acP, tiP, twP);

    cudaStreamWaitEvent(0, evJoin, 0);
    freq_kernel<<<dim3(SQ, BSZ), 256>>>(VbP, tiP, twP, CbP, CbhP);

    gemm_f16_kernel<<<dim3(HID / 128, (BSZ * SQ) / 128, 1), 256, 55296>>>(
        CbhP, WohP, WolP, bo, out, BSZ * SQ, HID, HID);
}

// round 17
// speedup vs baseline: 1.4219x; 1.4219x over previous
#include <cuda_runtime.h>
#include <cuda_bf16.h>
#include <cuda_fp16.h>
#include <math.h>
#include <stdint.h>

#define SQ   2048
#define HID  1024
#define NH   16
#define HD   64
#define BSZ  2
#define MFREQ (SQ/2 + 1)
#define KTOP 15
#define PKS  3072
#define LOG2E 1.4426950408889634f

__device__ float d_c[SQ];
__device__ float d_dcflag;
__device__ int   d_maskflag;
__device__ float d_Vbuf[BSZ * SQ * HID];
__device__ float d_Comb[BSZ * SQ * HID];
__device__ float d_ac  [BSZ * NH * SQ];
__device__ int   d_topi[BSZ * NH * KTOP];
__device__ float d_topw[BSZ * NH * KTOP];

__device__ __nv_bfloat16 d_chi[SQ], d_clo[SQ];
__device__ __nv_bfloat16 d_Chi [SQ * SQ],        d_Clo [SQ * SQ];
__device__ __nv_bfloat16 d_Xhi [BSZ * SQ * HID], d_Xlo [BSZ * SQ * HID];
__device__ __nv_bfloat16 d_Xfhi[BSZ * SQ * HID], d_Xflo[BSZ * SQ * HID];
__device__ __half        d_QKVhi[BSZ * SQ * PKS], d_QKVlo[BSZ * SQ * PKS];
__device__ __half        d_Cbh [BSZ * SQ * HID];
__device__ __nv_bfloat16 d_Wchi[HID * PKS], d_Wclo[HID * PKS];
__device__ float         d_bcat[PKS];
__device__ __half        d_Woh[HID * HID], d_Wol[HID * HID];

__device__ __forceinline__ void cp_async16(void* smem, const void* gmem) {
    unsigned s = (unsigned)__cvta_generic_to_shared(smem);
    asm volatile("cp.async.cg.shared.global [%0], [%1], 16;" :: "r"(s), "l"(gmem));
}
__device__ __forceinline__ void cp_commit() { asm volatile("cp.async.commit_group;"); }
__device__ __forceinline__ void cp_wait0()  { asm volatile("cp.async.wait_group 0;"); }
__device__ __forceinline__ void cp_wait1()  { asm volatile("cp.async.wait_group 1;"); }

__device__ __forceinline__ void mma16816(float* d, const uint32_t* a, const uint32_t* b) {
    asm volatile(
        "mma.sync.aligned.m16n8k16.row.col.f32.bf16.bf16.f32 "
        "{%0,%1,%2,%3}, {%4,%5,%6,%7}, {%8,%9}, {%0,%1,%2,%3};"
        : "+f"(d[0]), "+f"(d[1]), "+f"(d[2]), "+f"(d[3])
        : "r"(a[0]), "r"(a[1]), "r"(a[2]), "r"(a[3]), "r"(b[0]), "r"(b[1]));
}
__device__ __forceinline__ void mma16816h(float* d, const uint32_t* a, const uint32_t* b) {
    asm volatile(
        "mma.sync.aligned.m16n8k16.row.col.f32.f16.f16.f32 "
        "{%0,%1,%2,%3}, {%4,%5,%6,%7}, {%8,%9}, {%0,%1,%2,%3};"
        : "+f"(d[0]), "+f"(d[1]), "+f"(d[2]), "+f"(d[3])
        : "r"(a[0]), "r"(a[1]), "r"(a[2]), "r"(a[3]), "r"(b[0]), "r"(b[1]));
}
__device__ __forceinline__ void ldsm_x4(uint32_t* r, uint32_t addr) {
    asm volatile("ldmatrix.sync.aligned.m8n8.x4.shared.b16 {%0,%1,%2,%3}, [%4];"
        : "=r"(r[0]), "=r"(r[1]), "=r"(r[2]), "=r"(r[3]) : "r"(addr));
}
__device__ __forceinline__ void ldsm_x4t(uint32_t* r, uint32_t addr) {
    asm volatile("ldmatrix.sync.aligned.m8n8.x4.trans.shared.b16 {%0,%1,%2,%3}, [%4];"
        : "=r"(r[0]), "=r"(r[1]), "=r"(r[2]), "=r"(r[3]) : "r"(addr));
}
__device__ __forceinline__ void ldsm_x2t(uint32_t* r, uint32_t addr) {
    asm volatile("ldmatrix.sync.aligned.m8n8.x2.trans.shared.b16 {%0,%1}, [%2];"
        : "=r"(r[0]), "=r"(r[1]) : "r"(addr));
}
__device__ __forceinline__ uint32_t pack_h2(float a, float b) {
    __half2 t = __floats2half2_rn(a, b);
    return *(uint32_t*)&t;
}

__global__ void filter_kernel(const int* __restrict__ li_p, const int* __restrict__ nl_p,
                              float* __restrict__ c, float* __restrict__ dcflag,
                              __nv_bfloat16* __restrict__ chi, __nv_bfloat16* __restrict__ clo)
{
    int n = blockIdx.x * blockDim.x + threadIdx.x;
    if (n >= SQ) return;
    int li = *li_p;
    int nl = *nl_p;
    const double ALPHA = 0.5;
    int M = MFREQ;
    int p, q;
    if (ALPHA <= 1.0 / (double)nl) {
        p = (int)(M * (1.0 - (double)(li + 1) / (double)nl));
        q = (int)((double)p + (double)M / (double)nl);
    } else {
        p = (nl > 1) ? (int)(M * (1.0 - ALPHA) * (1.0 - (double)li / (double)(nl - 1))) : 0;
        q = (int)((double)p + ALPHA * (double)M);
    }
    p = max(0, min(p, M - 1));
    q = max(p + 1, min(q, M));
    double acc = 0.0;
    const double w2 = 2.0 / (double)SQ, w1 = 1.0 / (double)SQ;
    const double tpn = 6.283185307179586476925286766559 * (double)n / (double)SQ;
    for (int f = p; f < q; f++) {
        double wf = (f == 0 || f == M - 1) ? w1 : w2;
        acc += wf * cos(tpn * (double)f);
    }
    float cf = (float)acc;
    c[n] = cf;
    __nv_bfloat16 h = __float2bfloat16_rn(cf);
    chi[n] = h;
    clo[n] = __float2bfloat16_rn(cf - __bfloat162float(h));
    if (n == 0) *dcflag = (p == 0) ? 1.0f : 0.0f;
}

__global__ void cmat_kernel(__nv_bfloat16* __restrict__ Chi, __nv_bfloat16* __restrict__ Clo,
                            const __nv_bfloat16* __restrict__ chi, const __nv_bfloat16* __restrict__ clo)
{
    int idx = blockIdx.x * blockDim.x + threadIdx.x;
    int t = idx >> 11, s = idx & (SQ - 1);
    int tau = (t - s) & (SQ - 1);
    Chi[idx] = chi[tau];
    Clo[idx] = clo[tau];
}

__global__ void split_kernel(const float* __restrict__ in,
                             __nv_bfloat16* __restrict__ hi, __nv_bfloat16* __restrict__ lo, int n)
{
    int i = blockIdx.x * blockDim.x + threadIdx.x;
    if (i >= n) return;
    float f = in[i];
    __nv_bfloat16 h = __float2bfloat16_rn(f);
    hi[i] = h;
    lo[i] = __float2bfloat16_rn(f - __bfloat162float(h));
}

__global__ void wsplith_kernel(const float* __restrict__ in,
                               __half* __restrict__ hi, __half* __restrict__ lo, int n)
{
    int i = blockIdx.x * blockDim.x + threadIdx.x;
    if (i >= n) return;
    float f = in[i];
    __half h = __float2half_rn(f);
    hi[i] = h;
    lo[i] = __float2half_rn(f - __half2float(h));
}

__global__ void wsplit_kernel(const float* __restrict__ in,
                              __nv_bfloat16* __restrict__ hi, __nv_bfloat16* __restrict__ lo,
                              int colOff)
{
    int i = blockIdx.x * blockDim.x + threadIdx.x;
    int r = i >> 10, c = i & (HID - 1);
    float f = in[i];
    __nv_bfloat16 h = __float2bfloat16_rn(f);
    size_t o = (size_t)r * PKS + colOff + c;
    hi[o] = h;
    lo[o] = __float2bfloat16_rn(f - __bfloat162float(h));
}

__global__ void bcat_kernel(const float* __restrict__ bq, const float* __restrict__ bk,
                            const float* __restrict__ bv, float* __restrict__ bcat)
{
    int i = blockIdx.x * blockDim.x + threadIdx.x;
    const float* src = (i < HID) ? bq : (i < 2 * HID ? bk : bv);
    bcat[i] = src[i & (HID - 1)];
}

__global__ void zero_kernel(float* __restrict__ p, int n)
{
    int i = blockIdx.x * blockDim.x + threadIdx.x;
    if (i < n) p[i] = 0.f;
}

__global__ void setflag_kernel(int* __restrict__ flag) { *flag = 0; }

__global__ void maskcheck_kernel(const float4* __restrict__ m, int n4, int* __restrict__ flag)
{
    int i = blockIdx.x * blockDim.x + threadIdx.x;
    int stride = gridDim.x * blockDim.x;
    bool nz = false;
    for (; i < n4; i += stride) {
        float4 v = m[i];
        nz = nz || (v.x != 0.f) || (v.y != 0.f) || (v.z != 0.f) || (v.w != 0.f);
    }
    if (__syncthreads_or(nz) && threadIdx.x == 0)
        atomicOr(flag, 1);
}

// ---------------- bf16-split HMMA GEMM; optional fp16/bf16 hi+lo output ----------------
#define GA_STR 40
#define GB_STR 136
#define A_BUF_ELEMS (128 * GA_STR)
#define B_BUF_ELEMS (32 * GB_STR)
__global__ __launch_bounds__(256) void gemm_bf16_kernel(
    const __nv_bfloat16* __restrict__ Ahi, const __nv_bfloat16* __restrict__ Alo,
    const __nv_bfloat16* __restrict__ Bhi, const __nv_bfloat16* __restrict__ Blo,
    const float* __restrict__ bias, const float* __restrict__ bscalep,
    float* __restrict__ C,
    void* __restrict__ OhiV, void* __restrict__ OloV, int outHalf,
    int loColMin, int loColMax,
    int M, int N, int Nb, int K,
    long long sA, long long sB, long long sC)
{
    extern __shared__ __nv_bfloat16 sm[];
    __nv_bfloat16* AsHi = sm;
    __nv_bfloat16* AsLo = sm + 2 * A_BUF_ELEMS;
    __nv_bfloat16* BsHi = sm + 4 * A_BUF_ELEMS;
    __nv_bfloat16* BsLo = sm + 4 * A_BUF_ELEMS + 2 * B_BUF_ELEMS;
    uint32_t sbase = (uint32_t)__cvta_generic_to_shared(sm);

    int z = blockIdx.z;
    Ahi += (size_t)z * sA;  Alo += (size_t)z * sA;
    Bhi += (size_t)z * sB;  Blo += (size_t)z * sB;
    if (C) C += (size_t)z * sC;
    __nv_bfloat16* OhiB = (__nv_bfloat16*)OhiV;
    __nv_bfloat16* OloB = (__nv_bfloat16*)OloV;
    __half* OhiH = (__half*)OhiV;
    __half* OloH = (__half*)OloV;
    if (OhiV) {
        OhiB += (size_t)z * sC; OloB += (size_t)z * sC;
        OhiH += (size_t)z * sC; OloH += (size_t)z * sC;
    }

    int tid = threadIdx.x;
    int lane = tid & 31;
    int wid = tid >> 5;
    int mBase = (wid >> 2) * 64;
    int nBase = (wid & 3) * 32;
    int row0 = blockIdx.y * 128;
    int col0 = blockIdx.x * 128;

    float acc[4][4][4];
#pragma unroll
    for (int mf = 0; mf < 4; mf++)
#pragma unroll
        for (int nf = 0; nf < 4; nf++)
#pragma unroll
            for (int r = 0; r < 4; r++) acc[mf][nf][r] = 0.f;

    int ar = tid >> 1;
    int br = tid >> 3;
    const __nv_bfloat16* Ah0 = Ahi + (size_t)(row0 + ar) * K;
    const __nv_bfloat16* Al0 = Alo + (size_t)(row0 + ar) * K;

#define LOAD_TILES(buf, k0)                                                             \
    do {                                                                                \
        _Pragma("unroll")                                                               \
        for (int j = 0; j < 2; j++) {                                                   \
            int s = (tid & 1) * 2 + j;                                                  \
            cp_async16(&AsHi[(buf) * A_BUF_ELEMS + ar * GA_STR + s * 8],                \
                       Ah0 + (k0) + s * 8);                                             \
            cp_async16(&AsLo[(buf) * A_BUF_ELEMS + ar * GA_STR + s * 8],                \
                       Al0 + (k0) + s * 8);                                             \
            int sb = (tid & 7) * 2 + j;                                                 \
            cp_async16(&BsHi[(buf) * B_BUF_ELEMS + br * GB_STR + sb * 8],               \
                       Bhi + (size_t)((k0) + br) * Nb + col0 + sb * 8);                 \
            cp_async16(&BsLo[(buf) * B_BUF_ELEMS + br * GB_STR + sb * 8],               \
                       Blo + (size_t)((k0) + br) * Nb + col0 + sb * 8);                 \
        }                                                                               \
    } while (0)

    LOAD_TILES(0, 0);
    cp_commit();
    cp_wait0();
    __syncthreads();

    int nIter = K >> 5;
    int lr = lane & 15;
    int khalf = (lane >> 4) << 3;

    for (int it = 0; it < nIter; it++) {
        int buf = it & 1;
        if (it + 1 < nIter) {
            LOAD_TILES(buf ^ 1, (it + 1) << 5);
            cp_commit();
        }
        uint32_t aHiB = sbase + 2 * (buf * A_BUF_ELEMS);
        uint32_t aLoB = sbase + 2 * (2 * A_BUF_ELEMS + buf * A_BUF_ELEMS);
        uint32_t bHiB = sbase + 2 * (4 * A_BUF_ELEMS + buf * B_BUF_ELEMS);
        uint32_t bLoB = sbase + 2 * (4 * A_BUF_ELEMS + 2 * B_BUF_ELEMS + buf * B_BUF_ELEMS);
#pragma unroll
        for (int ks = 0; ks < 32; ks += 16) {
            uint32_t ahi[4][4], alo[4][4], bhi[4][2], blo[4][2];
#pragma unroll
            for (int mf = 0; mf < 4; mf++) {
                uint32_t off = 2 * ((mBase + mf * 16 + lr) * GA_STR + ks + khalf);
                ldsm_x4(ahi[mf], aHiB + off);
                ldsm_x4(alo[mf], aLoB + off);
            }
#pragma unroll
            for (int nf = 0; nf < 4; nf++) {
                uint32_t off = 2 * ((ks + lr) * GB_STR + nBase + nf * 8);
                ldsm_x2t(bhi[nf], bHiB + off);
                ldsm_x2t(blo[nf], bLoB + off);
            }
#pragma unroll
            for (int mf = 0; mf < 4; mf++)
#pragma unroll
                for (int nf = 0; nf < 4; nf++) {
                    mma16816(acc[mf][nf], ahi[mf], bhi[nf]);
                    mma16816(acc[mf][nf], ahi[mf], blo[nf]);
                    mma16816(acc[mf][nf], alo[mf], bhi[nf]);
                }
        }
        if (it + 1 < nIter) cp_wait0();
        __syncthreads();
    }

    float bscale = 0.f;
    if (bias) bscale = bscalep ? *bscalep : 1.f;

#pragma unroll
    for (int mf = 0; mf < 4; mf++) {
        int r0 = row0 + mBase + mf * 16 + (lane >> 2);
#pragma unroll
        for (int nf = 0; nf < 4; nf++) {
            int c0 = col0 + nBase + nf * 8 + (lane & 3) * 2;
            float b0 = 0.f, b1 = 0.f;
            if (bias) { b0 = bias[c0] * bscale; b1 = bias[c0 + 1] * bscale; }
            float v0 = acc[mf][nf][0] + b0, v1 = acc[mf][nf][1] + b1;
            float v2 = acc[mf][nf][2] + b0, v3 = acc[mf][nf][3] + b1;
            if (C) {
                float2 w0 = {v0, v1}, w1 = {v2, v3};
                *(float2*)&C[(size_t)r0 * N + c0]       = w0;
                *(float2*)&C[(size_t)(r0 + 8) * N + c0] = w1;
            }
            if (OhiV) {
                bool wantLo = (c0 >= loColMin) && (c0 < loColMax);
                if (outHalf) {
                    __half h0 = __float2half_rn(v0), h1 = __float2half_rn(v1);
                    __half h2 = __float2half_rn(v2), h3 = __float2half_rn(v3);
                    __half2 hv0 = {h0, h1}, hv1 = {h2, h3};
                    *(__half2*)&OhiH[(size_t)r0 * N + c0]       = hv0;
                    *(__half2*)&OhiH[(size_t)(r0 + 8) * N + c0] = hv1;
                    if (wantLo) {
                        __half2 lv0 = {__float2half_rn(v0 - __half2float(h0)),
                                       __float2half_rn(v1 - __half2float(h1))};
                        __half2 lv1 = {__float2half_rn(v2 - __half2float(h2)),
                                       __float2half_rn(v3 - __half2float(h3))};
                        *(__half2*)&OloH[(size_t)r0 * N + c0]       = lv0;
                        *(__half2*)&OloH[(size_t)(r0 + 8) * N + c0] = lv1;
                    }
                } else {
                    __nv_bfloat16 h0 = __float2bfloat16_rn(v0), h1 = __float2bfloat16_rn(v1);
                    __nv_bfloat16 h2 = __float2bfloat16_rn(v2), h3 = __float2bfloat16_rn(v3);
                    __nv_bfloat162 hv0 = {h0, h1}, hv1 = {h2, h3};
                    *(__nv_bfloat162*)&OhiB[(size_t)r0 * N + c0]       = hv0;
                    *(__nv_bfloat162*)&OhiB[(size_t)(r0 + 8) * N + c0] = hv1;
                    if (wantLo) {
                        __nv_bfloat162 lv0 = {__float2bfloat16_rn(v0 - __bfloat162float(h0)),
                                              __float2bfloat16_rn(v1 - __bfloat162float(h1))};
                        __nv_bfloat162 lv1 = {__float2bfloat16_rn(v2 - __bfloat162float(h2)),
                                              __float2bfloat16_rn(v3 - __bfloat162float(h3))};
                        *(__nv_bfloat162*)&OloB[(size_t)r0 * N + c0]       = lv0;
                        *(__nv_bfloat162*)&OloB[(size_t)(r0 + 8) * N + c0] = lv1;
                    }
                }
            }
        }
    }
}

// ---------------- fp16 2-term GEMM (outproj) ----------------
__global__ __launch_bounds__(256) void gemm_f16_kernel(
    const __half* __restrict__ Ah, const __half* __restrict__ Bhi, const __half* __restrict__ Blo,
    const float* __restrict__ bias, float* __restrict__ C, int M, int N, int K)
{
    extern __shared__ __half smh[];
    __half* AsH  = smh;
    __half* BsHi = smh + 2 * A_BUF_ELEMS;
    __half* BsLo = smh + 2 * A_BUF_ELEMS + 2 * B_BUF_ELEMS;
    uint32_t sbase = (uint32_t)__cvta_generic_to_shared(smh);

    int tid = threadIdx.x;
    int lane = tid & 31;
    int wid = tid >> 5;
    int mBase = (wid >> 2) * 64;
    int nBase = (wid & 3) * 32;
    int row0 = blockIdx.y * 128;
    int col0 = blockIdx.x * 128;

    float acc[4][4][4];
#pragma unroll
    for (int mf = 0; mf < 4; mf++)
#pragma unroll
        for (int nf = 0; nf < 4; nf++)
#pragma unroll
            for (int r = 0; r < 4; r++) acc[mf][nf][r] = 0.f;

    int ar = tid >> 1;
    int br = tid >> 3;
    const __half* A0 = Ah + (size_t)(row0 + ar) * K;

#define LOAD_TILES_H(buf, k0)                                                           \
    do {                                                                                \
        _Pragma("unroll")                                                               \
        for (int j = 0; j < 2; j++) {                                                   \
            int s = (tid & 1) * 2 + j;                                                  \
            cp_async16(&AsH[(buf) * A_BUF_ELEMS + ar * GA_STR + s * 8],                 \
                       A0 + (k0) + s * 8);                                              \
            int sb = (tid & 7) * 2 + j;                                                 \
            cp_async16(&BsHi[(buf) * B_BUF_ELEMS + br * GB_STR + sb * 8],               \
                       Bhi + (size_t)((k0) + br) * N + col0 + sb * 8);                  \
            cp_async16(&BsLo[(buf) * B_BUF_ELEMS + br * GB_STR + sb * 8],               \
                       Blo + (size_t)((k0) + br) * N + col0 + sb * 8);                  \
        }                                                                               \
    } while (0)

    LOAD_TILES_H(0, 0);
    cp_commit();
    cp_wait0();
    __syncthreads();

    int nIter = K >> 5;
    int lr = lane & 15;
    int khalf = (lane >> 4) << 3;

    for (int it = 0; it < nIter; it++) {
        int buf = it & 1;
        if (it + 1 < nIter) {
            LOAD_TILES_H(buf ^ 1, (it + 1) << 5);
            cp_commit();
        }
        uint32_t aB   = sbase + 2 * (buf * A_BUF_ELEMS);
        uint32_t bHiB = sbase + 2 * (2 * A_BUF_ELEMS + buf * B_BUF_ELEMS);
        uint32_t bLoB = sbase + 2 * (2 * A_BUF_ELEMS + 2 * B_BUF_ELEMS + buf * B_BUF_ELEMS);
#pragma unroll
        for (int ks = 0; ks < 32; ks += 16) {
            uint32_t ah[4][4], bhi[4][2], blo[4][2];
#pragma unroll
            for (int mf = 0; mf < 4; mf++) {
                uint32_t off = 2 * ((mBase + mf * 16 + lr) * GA_STR + ks + khalf);
                ldsm_x4(ah[mf], aB + off);
            }
#pragma unroll
            for (int nf = 0; nf < 4; nf++) {
                uint32_t off = 2 * ((ks + lr) * GB_STR + nBase + nf * 8);
                ldsm_x2t(bhi[nf], bHiB + off);
                ldsm_x2t(blo[nf], bLoB + off);
            }
#pragma unroll
            for (int mf = 0; mf < 4; mf++)
#pragma unroll
                for (int nf = 0; nf < 4; nf++) {
                    mma16816h(acc[mf][nf], ah[mf], bhi[nf]);
                    mma16816h(acc[mf][nf], ah[mf], blo[nf]);
                }
        }
        if (it + 1 < nIter) cp_wait0();
        __syncthreads();
    }

#pragma unroll
    for (int mf = 0; mf < 4; mf++) {
        int r0 = row0 + mBase + mf * 16 + (lane >> 2);
#pragma unroll
        for (int nf = 0; nf < 4; nf++) {
            int c0 = col0 + nBase + nf * 8 + (lane & 3) * 2;
            float b0 = bias[c0], b1 = bias[c0 + 1];
            float2 w0 = { acc[mf][nf][0] + b0, acc[mf][nf][1] + b1 };
            float2 w1 = { acc[mf][nf][2] + b0, acc[mf][nf][3] + b1 };
            *(float2*)&C[(size_t)r0 * N + c0]       = w0;
            *(float2*)&C[(size_t)(r0 + 8) * N + c0] = w1;
        }
    }
}

// ---------------- fp16 flash attention: 2-term QK, 1-term PV, exp2 softmax ----------------
#define FSTR 72
#define Q_ELEMS (128 * FSTR)
#define KV_BASE (2 * Q_ELEMS)
#define KV_ONE  (64 * FSTR)
#define KV_STRIDE (3 * KV_ONE)
#define SCS 66
#define ACB_OFF (2 * (KV_BASE + 2 * KV_STRIDE))
#define FLASH_SMEM (ACB_OFF + SQ * 4)
__global__ __launch_bounds__(256, 2) void flash_kernel(
    const __half* __restrict__ QKVhi, const __half* __restrict__ QKVlo,
    const float* __restrict__ mask, const int* __restrict__ maskflag,
    float* __restrict__ Comb, float* __restrict__ ac)
{
    extern __shared__ __half smh[];
    float* Stile = (float*)smh;
    float* acb   = (float*)((char*)smh + ACB_OFF);
    uint32_t sbase = (uint32_t)__cvta_generic_to_shared(smh);

    int tid = threadIdx.x;
    int lane = tid & 31, wid = tid >> 5;
    int qb = blockIdx.x, h = blockIdx.y, b = blockIdx.z;
    int t0 = qb * 128;
    int wr = wid * 16;
    const int useMask = *maskflag;
    const float SCL = 0.125f * LOG2E;

    size_t base = (size_t)b * SQ * PKS + h * HD;
    const __half* Qh = QKVhi + base;
    const __half* Kh = QKVhi + base + HID;
    const __half* Kl = QKVlo + base + HID;
    const __half* Vh = QKVhi + base + 2 * HID;
    const float* Mbase = mask + (size_t)b * SQ * SQ;
    float* acrow = ac + (size_t)(b * NH + h) * SQ;

#define LOAD_KV(bufi, kti)                                                              \
    do {                                                                                \
        int s0_ = (kti) * 64;                                                           \
        unsigned kvo_ = KV_BASE + (bufi) * KV_STRIDE;                                   \
        _Pragma("unroll")                                                               \
        for (int kk = 0; kk < 2; kk++) {                                                \
            int id_ = tid + kk * 256;                                                   \
            int r_ = id_ >> 3, c8_ = (id_ & 7) * 8;                                     \
            size_t src_ = (size_t)(s0_ + r_) * PKS + c8_;                               \
            unsigned dst_ = kvo_ + r_ * FSTR + c8_;                                     \
            cp_async16(&smh[dst_],              Kh + src_);                             \
            cp_async16(&smh[dst_ + KV_ONE],     Kl + src_);                             \
            cp_async16(&smh[dst_ + 2 * KV_ONE], Vh + src_);                             \
        }                                                                               \
    } while (0)

#pragma unroll
    for (int k = 0; k < 4; k++) {
        int id = tid + k * 256;
        int r = id >> 3, c8 = (id & 7) * 8;
        cp_async16(&smh[r * FSTR + c8], Qh + (size_t)(t0 + r) * PKS + c8);
    }
    cp_commit();
    LOAD_KV(0, 0);
    cp_commit();
    for (int i = tid; i < SQ; i += 256) acb[i] = 0.f;
    cp_wait1();
    __syncthreads();

    uint32_t qh[4][4];
    int lr = lane & 15, kh8 = (lane >> 4) * 8;
#pragma unroll
    for (int ks = 0; ks < 4; ks++)
        ldsm_x4(qh[ks], sbase + 2 * ((wr + lr) * FSTR + ks * 16 + kh8));
    cp_wait0();
    __syncthreads();

    float m0 = -INFINITY, m1 = -INFINITY, l0 = 0.f, l1 = 0.f;
    float o[8][4];
#pragma unroll
    for (int df = 0; df < 8; df++)
#pragma unroll
        for (int r = 0; r < 4; r++) o[df][r] = 0.f;

    int r4 = lane >> 2, c2 = (lane & 3) * 2;
    int qrow = t0 + wr + r4;
    int krL = ((lane >> 4) << 3) | (lane & 7);
    int kdL = ((lane >> 3) & 1) << 3;
    int vRow = lane & 15;
    int vSel = lane >> 4;

    int du = tid - 63;
    int drlo = du > 0 ? du : 0;
    int drhi = (du + 64 < 128) ? du + 64 : 128;
    const float* dbase = Stile - du;

    for (int kt = 0; kt < 32; kt++) {
        int s0 = kt * 64;
        int buf = kt & 1;
        bool has_next = (kt + 1 < 32);
        if (has_next) {
            LOAD_KV(buf ^ 1, kt + 1);
            cp_commit();
        }

        uint32_t kvbK = sbase + 2 * (KV_BASE + buf * KV_STRIDE);
        uint32_t kvbV = kvbK + 2 * (2 * KV_ONE);

        float s[8][4];
#pragma unroll
        for (int nf = 0; nf < 8; nf++)
#pragma unroll
            for (int r = 0; r < 4; r++) s[nf][r] = 0.f;
#pragma unroll
        for (int ks = 0; ks < 4; ks++) {
#pragma unroll
            for (int nf2 = 0; nf2 < 8; nf2 += 2) {
                uint32_t ko = kvbK + 2 * ((nf2 * 8 + krL) * FSTR + ks * 16 + kdL);
                uint32_t bh[4], bl[4];
                ldsm_x4(bh, ko);
                ldsm_x4(bl, ko + 2 * KV_ONE);
                mma16816h(s[nf2],     qh[ks], &bh[0]);
                mma16816h(s[nf2],     qh[ks], &bl[0]);
                mma16816h(s[nf2 + 1], qh[ks], &bh[2]);
                mma16816h(s[nf2 + 1], qh[ks], &bl[2]);
            }
        }

        {
            float* Sw0 = Stile + (wr + r4) * SCS + c2;
            float* Sw1 = Sw0 + 8 * SCS;
#pragma unroll
            for (int nf = 0; nf < 8; nf++) {
                float2 w0 = { s[nf][0], s[nf][1] };
                float2 w1 = { s[nf][2], s[nf][3] };
                *(float2*)(Sw0 + nf * 8) = w0;
                *(float2*)(Sw1 + nf * 8) = w1;
            }
        }

        const float* mrow0 = Mbase + (size_t)qrow * SQ + s0 + c2;
        const float* mrow1 = mrow0 + 8 * SQ;
        float mx0 = -INFINITY, mx1 = -INFINITY;
#pragma unroll
        for (int nf = 0; nf < 8; nf++) {
            float2 ma = {0.f, 0.f}, mb2 = {0.f, 0.f};
            if (useMask) {
                ma  = *(const float2*)(mrow0 + nf * 8);
                mb2 = *(const float2*)(mrow1 + nf * 8);
                ma.x *= LOG2E; ma.y *= LOG2E; mb2.x *= LOG2E; mb2.y *= LOG2E;
            }
            s[nf][0] = s[nf][0] * SCL + ma.x;
            s[nf][1] = s[nf][1] * SCL + ma.y;
            s[nf][2] = s[nf][2] * SCL + mb2.x;
            s[nf][3] = s[nf][3] * SCL + mb2.y;
            mx0 = fmaxf(mx0, fmaxf(s[nf][0], s[nf][1]));
            mx1 = fmaxf(mx1, fmaxf(s[nf][2], s[nf][3]));
        }
        mx0 = fmaxf(mx0, __shfl_xor_sync(0xffffffffu, mx0, 1));
        mx0 = fmaxf(mx0, __shfl_xor_sync(0xffffffffu, mx0, 2));
        mx1 = fmaxf(mx1, __shfl_xor_sync(0xffffffffu, mx1, 1));
        mx1 = fmaxf(mx1, __shfl_xor_sync(0xffffffffu, mx1, 2));
        float nm0 = fmaxf(m0, mx0), nm1 = fmaxf(m1, mx1);
        float cor0 = exp2f(m0 - nm0), cor1 = exp2f(m1 - nm1);
        m0 = nm0; m1 = nm1;

        uint32_t pa[4][4];
        float rs0 = 0.f, rs1 = 0.f;
#pragma unroll
        for (int kc = 0; kc < 4; kc++) {
            int n0 = 2 * kc, n1 = 2 * kc + 1;
            pa[kc][0] = pack_h2(exp2f(s[n0][0] - nm0), exp2f(s[n0][1] - nm0));
            pa[kc][1] = pack_h2(exp2f(s[n0][2] - nm1), exp2f(s[n0][3] - nm1));
            pa[kc][2] = pack_h2(exp2f(s[n1][0] - nm0), exp2f(s[n1][1] - nm0));
            pa[kc][3] = pack_h2(exp2f(s[n1][2] - nm1), exp2f(s[n1][3] - nm1));
            float2 u;
            u = __half22float2(*(__half2*)&pa[kc][0]); rs0 += u.x + u.y;
            u = __half22float2(*(__half2*)&pa[kc][2]); rs0 += u.x + u.y;
            u = __half22float2(*(__half2*)&pa[kc][1]); rs1 += u.x + u.y;
            u = __half22float2(*(__half2*)&pa[kc][3]); rs1 += u.x + u.y;
        }
        rs0 += __shfl_xor_sync(0xffffffffu, rs0, 1);
        rs0 += __shfl_xor_sync(0xffffffffu, rs0, 2);
        rs1 += __shfl_xor_sync(0xffffffffu, rs1, 1);
        rs1 += __shfl_xor_sync(0xffffffffu, rs1, 2);
        l0 = l0 * cor0 + rs0;
        l1 = l1 * cor1 + rs1;
#pragma unroll
        for (int df = 0; df < 8; df++) {
            o[df][0] *= cor0; o[df][1] *= cor0;
            o[df][2] *= cor1; o[df][3] *= cor1;
        }

#pragma unroll
        for (int kc = 0; kc < 4; kc++) {
#pragma unroll
            for (int df2 = 0; df2 < 8; df2 += 2) {
                uint32_t vo = kvbV + 2 * ((kc * 16 + vRow) * FSTR + (df2 + vSel) * 8);
                uint32_t vh[4];
                ldsm_x4t(vh, vo);
                mma16816h(o[df2],     pa[kc], &vh[0]);
                mma16816h(o[df2 + 1], pa[kc], &vh[2]);
            }
        }
        __syncthreads();

        if (tid < 191) {
            float sa = 0.f, sb = 0.f;
            int r = drlo;
            for (; r + 1 < drhi; r += 2) {
                sa += dbase[r * (SCS + 1)];
                sb += dbase[r * (SCS + 1) + (SCS + 1)];
            }
            if (r < drhi) sa += dbase[r * (SCS + 1)];
            int tau = (t0 - s0 + du) & (SQ - 1);
            acb[tau] += (sa + sb) * (1.f / 64.f);
        }
        if (has_next) cp_wait0();
        __syncthreads();
    }

    for (int i = tid; i < SQ; i += 256)
        atomicAdd(&acrow[i], acb[i]);

    float inv0 = 0.5f / l0, inv1 = 0.5f / l1;
    float* C0 = Comb + (size_t)b * SQ * HID + (size_t)qrow * HID + h * HD + c2;
#pragma unroll
    for (int df = 0; df < 8; df++) {
        float2 va = { o[df][0] * inv0, o[df][1] * inv0 };
        float2 vb = { o[df][2] * inv1, o[df][3] * inv1 };
        *(float2*)(C0 + df * 8)            = va;
        *(float2*)(C0 + 8 * HID + df * 8)  = vb;
    }
}

// ---------------- top-k ----------------
__global__ __launch_bounds__(256) void topk_kernel(
    const float* __restrict__ ac, int* __restrict__ topi, float* __restrict__ topw)
{
    int bh = blockIdx.x;
    __shared__ float svv[SQ];
    __shared__ float rv[256];
    __shared__ int ri[256];
    __shared__ float tvals[KTOP];
    __shared__ int tidxs[KTOP];
    int tid = threadIdx.x;

    for (int i = tid; i < SQ; i += 256)
        svv[i] = ac[(size_t)bh * SQ + i];
    __syncthreads();

    for (int t = 0; t < KTOP; t++) {
        float bv = -INFINITY;
        int bi = 0;
        for (int i = tid; i < SQ; i += 256) {
            float v = svv[i];
            if (v > bv || (v == bv && i < bi)) { bv = v; bi = i; }
        }
        rv[tid] = bv; ri[tid] = bi;
        __syncthreads();
        for (int st = 128; st > 0; st >>= 1) {
            if (tid < st) {
                float v2 = rv[tid + st]; int i2 = ri[tid + st];
                if (v2 > rv[tid] || (v2 == rv[tid] && i2 < ri[tid])) { rv[tid] = v2; ri[tid] = i2; }
            }
            __syncthreads();
        }
        if (tid == 0) {
            tvals[t] = rv[0]; tidxs[t] = ri[0];
            svv[ri[0]] = -INFINITY;
        }
        __syncthreads();
    }

    if (tid == 0) {
        float mx = tvals[0];
        float e[KTOP], ssum = 0.f;
#pragma unroll
        for (int t = 0; t < KTOP; t++) { e[t] = __expf(tvals[t] - mx); ssum += e[t]; }
        float inv = 1.f / ssum;
#pragma unroll
        for (int t = 0; t < KTOP; t++) {
            topw[bh * KTOP + t] = e[t] * inv;
            topi[bh * KTOP + t] = tidxs[t];
        }
    }
}

// ---------------- freq gather -> fp16 Cb for outproj ----------------
__global__ __launch_bounds__(256) void freq_kernel(
    const float* __restrict__ V, const int* __restrict__ topi,
    const float* __restrict__ topw, const float* __restrict__ Comb,
    __half* __restrict__ Cbh)
{
    int t = blockIdx.x, b = blockIdx.y;
    __shared__ int si[NH * KTOP];
    __shared__ float sw[NH * KTOP];
    int tid = threadIdx.x;
    if (tid < NH * KTOP) {
        si[tid] = topi[b * NH * KTOP + tid];
        sw[tid] = topw[b * NH * KTOP + tid];
    }
    __syncthreads();

    int c = tid * 4;
    int h = c >> 6;
    size_t off = ((size_t)b * SQ + t) * HID + c;
    float4 acc = *(const float4*)&Comb[off];
    const float* Vb = V + (size_t)b * SQ * HID;
#pragma unroll
    for (int j = 0; j < KTOP; j++) {
        int row = (t + si[h * KTOP + j]) & (SQ - 1);
        float w = 0.5f * sw[h * KTOP + j];
        float4 v = *(const float4*)&Vb[(size_t)row * HID + c];
        acc.x += w * v.x; acc.y += w * v.y; acc.z += w * v.z; acc.w += w * v.w;
    }
    *(__half2*)&Cbh[off]     = __floats2half2_rn(acc.x, acc.y);
    *(__half2*)&Cbh[off + 2] = __floats2half2_rn(acc.z, acc.w);
}

// ---------------- launcher (R15 topology: maskcheck on main, single fork for Vbuf/Wo) ----------------
extern "C" void kernel_launch(void* const* d_in, const int* in_sizes, int n_in,
                              void* d_out, int out_size)
{
    const float* X    = (const float*)d_in[0];
    const float* mask = (const float*)d_in[1];
    const float* Wq   = (const float*)d_in[2];
    const float* bq   = (const float*)d_in[3];
    const float* Wk   = (const float*)d_in[4];
    const float* bk   = (const float*)d_in[5];
    const float* Wv   = (const float*)d_in[6];
    const float* bv   = (const float*)d_in[7];
    const float* Wo   = (const float*)d_in[8];
    const float* bo   = (const float*)d_in[9];
    const int*   li   = (const int*)d_in[10];
    const int*   nl   = (const int*)d_in[11];
    float* out = (float*)d_out;

    float *cP, *dcP, *VbP, *CbP, *acP, *twP, *bcatP;
    int *tiP, *mfP;
    __nv_bfloat16 *chiP, *cloP, *ChiP, *CloP, *XhiP, *XloP, *XfhiP, *XfloP;
    __nv_bfloat16 *WchiP, *WcloP;
    __half *QKVhiP, *QKVloP, *CbhP, *WohP, *WolP;
    cudaGetSymbolAddress((void**)&cP,  d_c);
    cudaGetSymbolAddress((void**)&dcP, d_dcflag);
    cudaGetSymbolAddress((void**)&mfP, d_maskflag);
    cudaGetSymbolAddress((void**)&VbP, d_Vbuf);
    cudaGetSymbolAddress((void**)&CbP, d_Comb);
    cudaGetSymbolAddress((void**)&acP, d_ac);
    cudaGetSymbolAddress((void**)&tiP, d_topi);
    cudaGetSymbolAddress((void**)&twP, d_topw);
    cudaGetSymbolAddress((void**)&bcatP, d_bcat);
    cudaGetSymbolAddress((void**)&chiP, d_chi);
    cudaGetSymbolAddress((void**)&cloP, d_clo);
    cudaGetSymbolAddress((void**)&ChiP, d_Chi);
    cudaGetSymbolAddress((void**)&CloP, d_Clo);
    cudaGetSymbolAddress((void**)&XhiP, d_Xhi);
    cudaGetSymbolAddress((void**)&XloP, d_Xlo);
    cudaGetSymbolAddress((void**)&XfhiP, d_Xfhi);
    cudaGetSymbolAddress((void**)&XfloP, d_Xflo);
    cudaGetSymbolAddress((void**)&QKVhiP, d_QKVhi);
    cudaGetSymbolAddress((void**)&QKVloP, d_QKVlo);
    cudaGetSymbolAddress((void**)&CbhP, d_Cbh);
    cudaGetSymbolAddress((void**)&WchiP, d_Wchi);
    cudaGetSymbolAddress((void**)&WcloP, d_Wclo);
    cudaGetSymbolAddress((void**)&WohP, d_Woh);
    cudaGetSymbolAddress((void**)&WolP, d_Wol);

    const long long SH  = (long long)SQ * HID;
    const long long SH3 = (long long)SQ * PKS;
    const int NELT = BSZ * SQ * HID;
    const int WELT = HID * HID;

    static cudaStream_t s2 = nullptr;
    static cudaEvent_t evFork = nullptr, evJoin = nullptr;
    static bool init_done = false;
    if (!init_done) {
        cudaFuncSetAttribute(gemm_bf16_kernel, cudaFuncAttributeMaxDynamicSharedMemorySize, 75776);
        cudaFuncSetAttribute(gemm_f16_kernel,  cudaFuncAttributeMaxDynamicSharedMemorySize, 55296);
        cudaFuncSetAttribute(flash_kernel,     cudaFuncAttributeMaxDynamicSharedMemorySize, FLASH_SMEM);
        cudaStreamCreateWithFlags(&s2, cudaStreamNonBlocking);
        cudaEventCreateWithFlags(&evFork, cudaEventDisableTiming);
        cudaEventCreateWithFlags(&evJoin, cudaEventDisableTiming);
        init_done = true;
    }

    // main stream: prep chain (R15 ordering)
    setflag_kernel<<<1, 1>>>(mfP);
    maskcheck_kernel<<<2048, 256>>>((const float4*)mask, BSZ * SQ * SQ / 4, mfP);
    filter_kernel<<<8, 256>>>(li, nl, cP, dcP, chiP, cloP);
    cmat_kernel<<<(SQ * SQ) / 256, 256>>>(ChiP, CloP, chiP, cloP);
    split_kernel<<<NELT / 256, 256>>>(X, XhiP, XloP, NELT);
    wsplit_kernel<<<WELT / 256, 256>>>(Wq, WchiP, WcloP, 0);
    wsplit_kernel<<<WELT / 256, 256>>>(Wk, WchiP, WcloP, HID);
    wsplit_kernel<<<WELT / 256, 256>>>(Wv, WchiP, WcloP, 2 * HID);
    bcat_kernel<<<PKS / 256, 256>>>(bq, bk, bv, bcatP);

    // fork: side stream computes Vbuf + Wo split
    cudaEventRecord(evFork, 0);
    cudaStreamWaitEvent(s2, evFork, 0);
    gemm_bf16_kernel<<<dim3(HID / 128, SQ / 128, BSZ), 256, 75776, s2>>>(
        XhiP, XloP, WchiP + 2 * HID, WcloP + 2 * HID, bv, nullptr, VbP,
        nullptr, nullptr, 0, 0, 0, SQ, HID, PKS, HID, SH, 0, SH);
    wsplith_kernel<<<WELT / 256, 256, 0, s2>>>(Wo, WohP, WolP, WELT);
    cudaEventRecord(evJoin, s2);

    // main: Xf = C @ X -> bf16 hi/lo
    gemm_bf16_kernel<<<dim3(HID / 128, SQ / 128, BSZ), 256, 75776>>>(
        ChiP, CloP, XhiP, XloP, nullptr, nullptr, nullptr,
        XfhiP, XfloP, 0, 0, HID, SQ, HID, HID, SQ, 0, SH, SH);

    // merged Q|K|V projections -> fp16 QKV; lo only for K columns
    gemm_bf16_kernel<<<dim3(PKS / 128, SQ / 128, BSZ), 256, 75776>>>(
        XfhiP, XfloP, WchiP, WcloP, bcatP, dcP, nullptr,
        QKVhiP, QKVloP, 1, HID, 2 * HID, SQ, PKS, PKS, HID, SH, 0, SH3);

    zero_kernel<<<(BSZ * NH * SQ) / 256, 256>>>(acP, BSZ * NH * SQ);
    flash_kernel<<<dim3(SQ / 128, NH, BSZ), 256, FLASH_SMEM>>>(
        QKVhiP, QKVloP, mask, mfP, CbP, acP);

    topk_kernel<<<BSZ * NH, 256>>>(acP, tiP, twP);

    cudaStreamWaitEvent(0, evJoin, 0);
    freq_kernel<<<dim3(SQ, BSZ), 256>>>(VbP, tiP, twP, CbP, CbhP);

    gemm_f16_kernel<<<dim3(HID / 128, (BSZ * SQ) / 128, 1), 256, 55296>>>(
        CbhP, WohP, WolP, bo, out, BSZ * SQ, HID, HID);
}